// round 12
// baseline (speedup 1.0000x reference)
#include <cuda_runtime.h>
#include <cuda_bf16.h>

// Problem geometry
#define BATCH   8
#define HIN     1024
#define WIN     1024
#define HC      1025                 // code-grid rows
#define WC      1025                 // code-grid cols
#define CELLS   (HC * WC)            // 1,050,625 cells per batch
#define WCP     1028                 // padded code-row stride (mult of 4)
#define CSTRIDE (HC * WCP)           // per-batch code stride
#define RPB1    8                    // rows per phase-1 chunk
#define NBB1    129                  // chunks per batch
#define NCHUNK  (BATCH * NBB1)       // 1032 phase-1 chunks
#define TPB     256
#define NBLK    1184                 // 8 CTAs/SM x 148 SMs — co-resident at 100% occ
#define NWARPS  (NBLK * 8)           // 9472 phase-2 warps
#define GROWS   (BATCH * HC)         // 8200 global rows
#define NROWS   (2 * BATCH * CELLS)  // 16,810,000 output rows (float4 each)
#define ZSTART  (BATCH * CELLS)      // 8,405,000 = E[total]

// -------- scratch (static device globals; no allocation allowed) ----------
__device__ unsigned char g_codes[(size_t)BATCH * CSTRIDE];
__device__ unsigned int  g_cnt1[GROWS];
__device__ unsigned int  g_cnt2[GROWS];
__device__ unsigned int  g_off1[GROWS];
__device__ unsigned int  g_off2[GROWS];
__device__ unsigned int  g_total;
__device__ unsigned int  g_arrive;   // 0 -> NBLK -> 2*NBLK -> reset 0
__device__ unsigned int  g_depart;   // reset bookkeeping

// Midpoint offsets per code (FIRST table): row = [y+f.x, x+f.y, y+f.z, x+f.w]
__constant__ float4 c_F[16] = {
    { 0.0f,  0.0f,  0.0f,  0.0f},  // 0  (invalid)
    { 0.0f, -0.5f,  0.5f,  0.0f},  // 1
    { 0.5f,  0.0f,  0.0f,  0.5f},  // 2
    { 0.0f, -0.5f,  0.0f,  0.5f},  // 3
    { 0.0f,  0.5f, -0.5f,  0.0f},  // 4
    { 0.0f, -0.5f,  0.5f,  0.0f},  // 5
    { 0.5f,  0.0f, -0.5f,  0.0f},  // 6
    { 0.0f, -0.5f, -0.5f,  0.0f},  // 7
    {-0.5f,  0.0f,  0.0f, -0.5f},  // 8
    {-0.5f,  0.0f,  0.5f,  0.0f},  // 9
    { 0.5f,  0.0f,  0.0f,  0.5f},  // 10
    {-0.5f,  0.0f,  0.0f,  0.5f},  // 11
    { 0.0f,  0.5f,  0.0f, -0.5f},  // 12
    { 0.0f,  0.5f,  0.5f,  0.0f},  // 13
    { 0.5f,  0.0f,  0.0f, -0.5f},  // 14
    { 0.0f,  0.0f,  0.0f,  0.0f},  // 15 (invalid)
};
// SECOND[5] = (0, 0.5, -0.5, 0), SECOND[10] = (-0.5, 0, 0, -0.5) inlined.

__global__ __launch_bounds__(TPB, 8)
void ms_fused(const float* __restrict__ in, float* __restrict__ out, int out_size)
{
    float4* __restrict__ out4 = (float4*)out;
    const int bk   = blockIdx.x;
    const int t    = threadIdx.x;
    const int lane = t & 31;
    const int wid  = t >> 5;

    __shared__ unsigned r1s[RPB1][8], r2s[RPB1][8];

    // ================= Phase 1: codes + per-row counts =====================
    for (int cidx = bk; cidx < NCHUNK; cidx += NBLK) {
        const int b     = cidx / NBB1;
        const int chunk = cidx - b * NBB1;
        const int y0    = chunk * RPB1;
        const int yend  = min(y0 + RPB1, HC);
        const float* __restrict__ img = in + (size_t)b * HIN * WIN;
        unsigned char* __restrict__ crow0 = g_codes + (size_t)b * CSTRIDE;
        const int col = 4 * t;

        const float* rA = img + (size_t)max(min(y0 - 1, HIN - 1), 0) * WIN;
        float4 vA = *(const float4*)(rA + col);
        float lmA = __shfl_up_sync(0xffffffffu, vA.w, 1);
        if (lane == 0) lmA = (col > 0) ? rA[col - 1] : vA.x;

        for (int y = y0; y < yend; y++) {
            const float* rB = img + (size_t)min(y, HIN - 1) * WIN;
            float4 vB = *(const float4*)(rB + col);
            float lmB = __shfl_up_sync(0xffffffffu, vB.w, 1);
            if (lane == 0) lmB = (col > 0) ? rB[col - 1] : vB.x;

            const float la[4] = {lmA, vA.x, vA.y, vA.z};
            const float ra[4] = {vA.x, vA.y, vA.z, vA.w};
            const float lb[4] = {lmB, vB.x, vB.y, vB.z};
            const float rb[4] = {vB.x, vB.y, vB.z, vB.w};

            unsigned packed = 0, c1 = 0, c2 = 0;
            #pragma unroll
            for (int j = 0; j < 4; j++) {
                unsigned code = (lb[j] > 0.0f ? 1u : 0u) | (rb[j] > 0.0f ? 2u : 0u) |
                                (ra[j] > 0.0f ? 4u : 0u) | (la[j] > 0.0f ? 8u : 0u);
                packed |= code << (8 * j);
                c1 += (code - 1u) < 14u;
                c2 += (code == 5u) | (code == 10u);
            }
            unsigned char* crow = crow0 + (size_t)y * WCP;
            *(unsigned int*)(crow + col) = packed;
            if (t == TPB - 1) {              // cell x = 1024 (clamped both sides)
                unsigned code = (vB.w > 0.0f ? 3u : 0u) | (vA.w > 0.0f ? 12u : 0u);
                crow[1024] = (unsigned char)code;
                c1 += (code - 1u) < 14u;     // codes {0,3,12,15}: never table-2
            }
            const unsigned s1 = __reduce_add_sync(0xffffffffu, c1);
            const unsigned s2 = __reduce_add_sync(0xffffffffu, c2);
            if (lane == 0) { r1s[y - y0][wid] = s1; r2s[y - y0][wid] = s2; }
            vA = vB; lmA = lmB;              // row reuse: bottom(y) == top(y+1)
        }
        __syncthreads();
        if (t < yend - y0) {
            unsigned t1 = 0, t2 = 0;
            #pragma unroll
            for (int w = 0; w < 8; w++) { t1 += r1s[t][w]; t2 += r2s[t][w]; }
            g_cnt1[b * HC + y0 + t] = t1;
            g_cnt2[b * HC + y0 + t] = t2;
        }
        __syncthreads();
    }

    // speculative zero of [ZSTART, NROWS) — overlaps other blocks' phase 1
    {
        const unsigned zn = (unsigned)(NROWS - ZSTART);
        const unsigned cz = (zn + NBLK - 1) / NBLK;
        const unsigned s  = (unsigned)ZSTART + (unsigned)bk * cz;
        const unsigned e  = min(s + cz, (unsigned)NROWS);
        const float4 z = make_float4(0.0f, 0.0f, 0.0f, 0.0f);
        for (unsigned i = s + t; i < e; i += TPB) __stwt(&out4[i], z);
    }

    // ================= grid barrier + inline scan ==========================
    __shared__ unsigned slast;
    if (t == 0) {
        __threadfence();                     // publish codes + counts + zeros
        const unsigned old = atomicAdd(&g_arrive, 1u);
        slast = (old == (unsigned)(NBLK - 1)) ? 1u : 0u;
    }
    __syncthreads();

    if (slast) {                             // uniform across the block
        __threadfence();                     // acquire all g_cnt writes
        __shared__ unsigned tot[16], gbs[17];

        // Sweep A: ALL 16 group totals first (warp wid owns groups 2w, 2w+1)
        #pragma unroll
        for (int rep = 0; rep < 2; rep++) {
            const int g = wid * 2 + rep;
            const unsigned* __restrict__ cnt = (g & 1) ? g_cnt2 : g_cnt1;
            const int base = (g >> 1) * HC;
            unsigned s = 0;
            for (int i = lane; i < HC; i += 32) s += cnt[base + i];
            s = __reduce_add_sync(0xffffffffu, s);
            if (lane == 0) tot[g] = s;
        }
        __syncthreads();                     // ALL tot[] valid now
        if (t == 0) {
            unsigned acc = 0;
            #pragma unroll
            for (int q = 0; q < 16; q++) { gbs[q] = acc; acc += tot[q]; }
            gbs[16] = acc;
            g_total = acc;
        }
        __syncthreads();

        // Sweep B: exclusive offsets per group (reload counts; L2-hot)
        #pragma unroll
        for (int rep = 0; rep < 2; rep++) {
            const int g = wid * 2 + rep;
            const unsigned* __restrict__ cnt = (g & 1) ? g_cnt2 : g_cnt1;
            unsigned*       __restrict__ off = (g & 1) ? g_off2 : g_off1;
            const int base = (g >> 1) * HC;
            unsigned carry = gbs[g];
            for (int i0 = 0; i0 < HC; i0 += 32) {
                const int i = i0 + lane;
                const unsigned v = (i < HC) ? cnt[base + i] : 0u;
                unsigned incl = v;
                #pragma unroll
                for (int o = 1; o < 32; o <<= 1) {
                    const unsigned u = __shfl_up_sync(0xffffffffu, incl, o);
                    if (lane >= o) incl += u;
                }
                if (i < HC) off[base + i] = carry + incl - v;
                carry += __shfl_sync(0xffffffffu, incl, 31);
            }
        }
        __syncthreads();
        if (t < BATCH && out_size >= NROWS * 4 + BATCH)
            out[(size_t)NROWS * 4 + t] = (float)(tot[2 * t] + tot[2 * t + 1]);
        __syncthreads();
        if (t == 0) {
            __threadfence();                 // publish offsets + g_total
            atomicExch(&g_arrive, 2u * NBLK);
        }
    }

    if (t == 0) {
        if (!slast) {
            volatile unsigned* p = &g_arrive;
            while (*p < 2u * NBLK) __nanosleep(128);
        }
        __threadfence();                     // acquire offsets
        const unsigned old = atomicAdd(&g_depart, 1u);
        if (old == (unsigned)(NBLK - 1)) {   // last departer resets for replay
            atomicExch(&g_arrive, 0u);
            atomicExch(&g_depart, 0u);
        }
    }
    __syncthreads();

    // ================= Phase 2: warp-per-row ballot compaction =============
    const unsigned lanelt = (1u << lane) - 1u;
    const int gw = bk * 8 + wid;
    for (int row = gw; row < GROWS; row += NWARPS) {
        const int b = row / HC;
        const int y = row - b * HC;
        const unsigned char* __restrict__ crow =
            g_codes + (size_t)b * CSTRIDE + (size_t)y * WCP;
        unsigned o1 = g_off1[row];
        unsigned o2 = g_off2[row];
        const float fy = (float)y;
        #pragma unroll 3
        for (int i = 0; i < 33; i++) {
            const int x = i * 32 + lane;
            const unsigned code = (x < WC) ? (unsigned)crow[x] : 0u;
            const bool v1 = (code - 1u) < 14u;
            const bool v2 = (code == 5u) | (code == 10u);
            const unsigned m1 = __ballot_sync(0xffffffffu, v1);
            const unsigned m2 = __ballot_sync(0xffffffffu, v2);
            const float cx = (float)x;
            if (v1) {
                const float4 f = c_F[code];
                __stwt(&out4[o1 + __popc(m1 & lanelt)],
                       make_float4(fy + f.x, cx + f.y, fy + f.z, cx + f.w));
            }
            if (v2) {
                const float4 w = (code == 5u)
                    ? make_float4(fy, cx + 0.5f, fy - 0.5f, cx)
                    : make_float4(fy - 0.5f, cx, fy, cx - 0.5f);
                __stwt(&out4[o2 + __popc(m2 & lanelt)], w);
            }
            o1 += __popc(m1);
            o2 += __popc(m2);
        }
    }

    // residual zero: [g_total, ZSTART) when total < ZSTART
    const unsigned total = g_total;
    if (total < (unsigned)ZSTART) {
        const unsigned tail = (unsigned)ZSTART - total;
        const unsigned cz   = (tail + NBLK - 1) / NBLK;
        const unsigned s    = total + (unsigned)bk * cz;
        const unsigned e    = min(s + cz, (unsigned)ZSTART);
        const float4 z = make_float4(0.0f, 0.0f, 0.0f, 0.0f);
        for (unsigned i = s + t; i < e; i += TPB) __stwt(&out4[i], z);
    }
}

// ---------------------------------------------------------------------------
extern "C" void kernel_launch(void* const* d_in, const int* in_sizes, int n_in,
                              void* d_out, int out_size)
{
    const float* coarse = (const float*)d_in[0];
    float* out = (float*)d_out;
    ms_fused<<<NBLK, TPB>>>(coarse, out, out_size);
}

// round 13
// speedup vs baseline: 1.2957x; 1.2957x over previous
#include <cuda_runtime.h>
#include <cuda_bf16.h>
#include <cstdint>

// Problem geometry
#define BATCH   8
#define HIN     1024
#define WIN     1024
#define HC      1025               // code-grid rows
#define WC      1025               // code-grid cols
#define CELLS   (HC * WC)          // 1,050,625 cells per batch
#define WCP     1028               // padded code-row stride (mult of 4)
#define CSTRIDE (HC * WCP)         // per-batch code stride
#define RPB1    8                  // rows per pass1 block
#define NBB1    129                // pass1 chunks per batch: ceil(1025/8)
#define NBLK1   (BATCH * NBB1)     // 1032 pass1 blocks
#define RPB2    2                  // rows per pass2 block (wave balance)
#define NBB2    513                // pass2 chunks per batch: ceil(1025/2)
#define NBLK2   (BATCH * NBB2)     // 4104 pass2 blocks
#define TPB     256
#define NROWS   (2 * BATCH * CELLS)  // 16,810,000 output rows (float4 each)

// -------- scratch (static device globals; no allocation allowed) ----------
__device__ unsigned char g_codes[(size_t)BATCH * CSTRIDE];
__device__ unsigned int  g_cnt1[NBLK2];
__device__ unsigned int  g_cnt2[NBLK2];
__device__ unsigned int  g_off1[NBLK2];
__device__ unsigned int  g_off2[NBLK2];
__device__ unsigned int  g_total;
__device__ unsigned int  g_done;     // zero-init; reset by last block each launch

// Midpoint offsets per code (FIRST table): row = [y+f.x, x+f.y, y+f.z, x+f.w]
__constant__ float4 c_F[16] = {
    { 0.0f,  0.0f,  0.0f,  0.0f},  // 0  (invalid)
    { 0.0f, -0.5f,  0.5f,  0.0f},  // 1
    { 0.5f,  0.0f,  0.0f,  0.5f},  // 2
    { 0.0f, -0.5f,  0.0f,  0.5f},  // 3
    { 0.0f,  0.5f, -0.5f,  0.0f},  // 4
    { 0.0f, -0.5f,  0.5f,  0.0f},  // 5
    { 0.5f,  0.0f, -0.5f,  0.0f},  // 6
    { 0.0f, -0.5f, -0.5f,  0.0f},  // 7
    {-0.5f,  0.0f,  0.0f, -0.5f},  // 8
    {-0.5f,  0.0f,  0.5f,  0.0f},  // 9
    { 0.5f,  0.0f,  0.0f,  0.5f},  // 10
    {-0.5f,  0.0f,  0.0f,  0.5f},  // 11
    { 0.0f,  0.5f,  0.0f, -0.5f},  // 12
    { 0.0f,  0.5f,  0.5f,  0.0f},  // 13
    { 0.5f,  0.0f,  0.0f, -0.5f},  // 14
    { 0.0f,  0.0f,  0.0f,  0.0f},  // 15 (invalid)
};
// SECOND[5] = (0, 0.5, -0.5, 0), SECOND[10] = (-0.5, 0, 0, -0.5) inlined.

// -------- bulk async copy (UBLKCP): shared -> global, zero per-element ops -
__device__ __forceinline__ uint32_t smem_u32(const void* p) {
    uint32_t a;
    asm("{ .reg .u64 t; cvta.to.shared.u64 t, %1; cvt.u32.u64 %0, t; }"
        : "=r"(a) : "l"(p));
    return a;
}
__device__ __forceinline__ void bulk_store(void* gdst, uint32_t ssrc, unsigned bytes) {
    asm volatile("cp.async.bulk.global.shared::cta.bulk_group [%0], [%1], %2;"
        :: "l"(gdst), "r"(ssrc), "r"(bytes) : "memory");
}
#define BULK_COMMIT()     asm volatile("cp.async.bulk.commit_group;" ::: "memory")
#define BULK_WAIT_READ0() asm volatile("cp.async.bulk.wait_group.read 0;" ::: "memory")
#define BULK_WAIT0()      asm volatile("cp.async.bulk.wait_group 0;" ::: "memory")
#define FENCE_ASYNC()     asm volatile("fence.proxy.async.shared::cta;" ::: "memory")

// ------- Pass 1: codes + per-2-row-subchunk counts + inline final scan -----
__global__ __launch_bounds__(TPB, 8)
void ms_pass1(const float* __restrict__ in, float* __restrict__ out, int out_size)
{
    const int bk    = blockIdx.x;
    const int b     = bk / NBB1;
    const int chunk = bk - b * NBB1;
    const int y0    = chunk * RPB1;
    const float* __restrict__ img = in + (size_t)b * HIN * WIN;
    unsigned char* __restrict__ crow0 = g_codes + (size_t)b * CSTRIDE;

    const int t    = threadIdx.x;
    const int col  = 4 * t;
    const int lane = t & 31;
    const int wid  = t >> 5;
    __shared__ unsigned r1[8], r2[8];

    const float* rA = img + (size_t)max(min(y0 - 1, HIN - 1), 0) * WIN;
    float4 vA = *(const float4*)(rA + col);
    float lmA = __shfl_up_sync(0xffffffffu, vA.w, 1);
    if (lane == 0) lmA = (col > 0) ? rA[col - 1] : vA.x;

    #pragma unroll
    for (int sub = 0; sub < 4; sub++) {
        const int ys = y0 + 2 * sub;
        if (ys >= HC) break;
        const int ye = min(ys + 2, HC);
        unsigned c1 = 0, c2 = 0;

        for (int y = ys; y < ye; y++) {
            const float* rB = img + (size_t)min(y, HIN - 1) * WIN;
            float4 vB = *(const float4*)(rB + col);
            float lmB = __shfl_up_sync(0xffffffffu, vB.w, 1);
            if (lane == 0) lmB = (col > 0) ? rB[col - 1] : vB.x;

            const float la[4] = {lmA, vA.x, vA.y, vA.z};
            const float ra[4] = {vA.x, vA.y, vA.z, vA.w};
            const float lb[4] = {lmB, vB.x, vB.y, vB.z};
            const float rb[4] = {vB.x, vB.y, vB.z, vB.w};

            unsigned packed = 0;
            #pragma unroll
            for (int j = 0; j < 4; j++) {
                unsigned code = (lb[j] > 0.0f ? 1u : 0u) | (rb[j] > 0.0f ? 2u : 0u) |
                                (ra[j] > 0.0f ? 4u : 0u) | (la[j] > 0.0f ? 8u : 0u);
                packed |= code << (8 * j);
                c1 += (code - 1u) < 14u;
                c2 += (code == 5u) | (code == 10u);
            }
            unsigned char* crow = crow0 + (size_t)y * WCP;
            *(unsigned int*)(crow + col) = packed;
            if (t == TPB - 1) {
                unsigned code = (vB.w > 0.0f ? 3u : 0u) | (vA.w > 0.0f ? 12u : 0u);
                crow[1024] = (unsigned char)code;
                c1 += (code - 1u) < 14u;
            }
            vA = vB; lmA = lmB;
        }

        unsigned s1 = __reduce_add_sync(0xffffffffu, c1);
        unsigned s2 = __reduce_add_sync(0xffffffffu, c2);
        __syncthreads();
        if (lane == 0) { r1[wid] = s1; r2[wid] = s2; }
        __syncthreads();
        if (t == 0) {
            unsigned t1 = 0, t2 = 0;
            #pragma unroll
            for (int i = 0; i < 8; i++) { t1 += r1[i]; t2 += r2[i]; }
            const int idx = b * NBB2 + chunk * 4 + sub;
            g_cnt1[idx] = t1;
            g_cnt2[idx] = t2;
        }
    }

    // ---- last-block-done: final block performs the global scan inline -----
    __shared__ unsigned slast;
    if (t == 0) {
        __threadfence();
        const bool last = (atomicAdd(&g_done, 1u) == (unsigned)(NBLK1 - 1));
        if (last) g_done = 0;
        slast = last ? 1u : 0u;
    }
    __syncthreads();
    if (!slast) return;
    __threadfence();

    __shared__ unsigned tot[16], gbs[17];
    #pragma unroll
    for (int rep = 0; rep < 2; rep++) {
        const int g = wid * 2 + rep;
        const unsigned* __restrict__ cnt = (g & 1) ? g_cnt2 : g_cnt1;
        const int base = (g >> 1) * NBB2;
        const int i0 = lane * 17;
        unsigned s = 0;
        #pragma unroll
        for (int j = 0; j < 17; j++) {
            const int i = i0 + j;
            if (i < NBB2) s += cnt[base + i];
        }
        s = __reduce_add_sync(0xffffffffu, s);
        if (lane == 0) tot[g] = s;
    }
    __syncthreads();
    if (t == 0) {
        unsigned acc = 0;
        #pragma unroll
        for (int g = 0; g < 16; g++) { gbs[g] = acc; acc += tot[g]; }
        gbs[16] = acc;
        g_total = acc;
    }
    __syncthreads();
    if (t < BATCH && out_size >= NROWS * 4 + BATCH)
        out[(size_t)NROWS * 4 + t] = (float)(tot[2 * t] + tot[2 * t + 1]);

    #pragma unroll
    for (int rep = 0; rep < 2; rep++) {
        const int g = wid * 2 + rep;
        const unsigned* __restrict__ cnt = (g & 1) ? g_cnt2 : g_cnt1;
        unsigned*       __restrict__ off = (g & 1) ? g_off2 : g_off1;
        const int base = (g >> 1) * NBB2;
        const int i0 = lane * 17;
        unsigned v[17];
        unsigned s = 0;
        #pragma unroll
        for (int j = 0; j < 17; j++) {
            const int i = i0 + j;
            v[j] = (i < NBB2) ? cnt[base + i] : 0u;
            s += v[j];
        }
        unsigned incl = s;
        #pragma unroll
        for (int o = 1; o < 32; o <<= 1) {
            const unsigned u = __shfl_up_sync(0xffffffffu, incl, o);
            if (lane >= o) incl += u;
        }
        unsigned run = gbs[g] + incl - s;
        #pragma unroll
        for (int j = 0; j < 17; j++) {
            const int i = i0 + j;
            if (i < NBB2) off[base + i] = run;
            run += v[j];
        }
    }
}

// ------ Pass 2: smem staging + cp.async.bulk flush + bulk tail zero --------
__global__ __launch_bounds__(TPB, 6)
void ms_pass2(float4* __restrict__ out4)
{
    __shared__ unsigned ws[8];
    __shared__ unsigned sh_n;
    __shared__ float4 buf1[1026];
    __shared__ float4 buf2[1026];

    const int bk   = blockIdx.x;
    const int b    = bk / NBB2;
    const int ci   = bk - b * NBB2;
    const int y0   = ci * RPB2;
    const int nrows = min(y0 + RPB2, HC) - y0;
    const unsigned char* __restrict__ crow0 = g_codes + (size_t)b * CSTRIDE;

    const int t = threadIdx.x;
    const unsigned lane = t & 31u, wid = t >> 5;
    const uint32_t sbuf1 = smem_u32(buf1);
    const uint32_t sbuf2 = smem_u32(buf2);

    unsigned off1 = g_off1[bk];
    unsigned off2 = g_off2[bk];

    // prefetch both rows' code words
    unsigned packs[2], cXs[2];
    #pragma unroll
    for (int r = 0; r < 2; r++) {
        if (r < nrows) {
            const unsigned char* crow = crow0 + (size_t)(y0 + r) * WCP;
            packs[r] = *(const unsigned int*)(crow + 4 * t);
            cXs[r]   = (t == TPB - 1) ? (unsigned)crow[1024] : 0u;
        } else { packs[r] = 0u; cXs[r] = 0u; }
    }

    #pragma unroll
    for (int r = 0; r < 2; r++) {
        if (r >= nrows) break;
        const int y = y0 + r;
        const unsigned packed = packs[r];
        unsigned cd[4];
        cd[0] =  packed        & 255u;
        cd[1] = (packed >>  8) & 255u;
        cd[2] = (packed >> 16) & 255u;
        cd[3] =  packed >> 24;
        const unsigned cX = cXs[r];

        unsigned c1 = 0, c2 = 0;
        #pragma unroll
        for (int j = 0; j < 4; j++) {
            c1 += (cd[j] - 1u) < 14u;
            c2 += (cd[j] == 5u) | (cd[j] == 10u);
        }
        c1 += (cX - 1u) < 14u;

        // block exclusive scan (16-bit packed: c1 | c2<<16)
        const unsigned v = c1 | (c2 << 16);
        unsigned inc = v;
        #pragma unroll
        for (int o = 1; o < 32; o <<= 1) {
            const unsigned u = __shfl_up_sync(0xffffffffu, inc, o);
            if (lane >= (unsigned)o) inc += u;
        }
        if (lane == 31) ws[wid] = inc;
        __syncthreads();                        // (A) ws visible
        if (t == 0) {
            unsigned acc = 0;
            #pragma unroll
            for (int i = 0; i < 8; i++) { const unsigned q = ws[i]; ws[i] = acc; acc += q; }
        }
        __syncthreads();                        // (B)
        const unsigned ex = inc - v + ws[wid];
        if (t == TPB - 1) sh_n = ex + v;
        unsigned p1 = ex & 0xffffu;
        unsigned p2 = ex >> 16;

        // wait until prior row's bulk copies have READ the buffers
        if (t == 0) BULK_WAIT_READ0();
        __syncthreads();                        // (C) safe to overwrite bufs; sh_n visible

        const float fy = (float)y;
        const float fx = (float)(4 * t);
        #pragma unroll
        for (int j = 0; j < 4; j++) {
            const unsigned code = cd[j];
            const float cx = fx + (float)j;
            if ((code - 1u) < 14u) {
                const float4 f = c_F[code];
                buf1[p1++] = make_float4(fy + f.x, cx + f.y, fy + f.z, cx + f.w);
            }
            if (code == 5u)
                buf2[p2++] = make_float4(fy, cx + 0.5f, fy - 0.5f, cx);
            else if (code == 10u)
                buf2[p2++] = make_float4(fy - 0.5f, cx, fy, cx - 0.5f);
        }
        if (t == TPB - 1 && (cX - 1u) < 14u) {
            const float4 f = c_F[cX];
            buf1[p1++] = make_float4(fy + f.x, 1024.0f + f.y, fy + f.z, 1024.0f + f.w);
        }
        __syncthreads();                        // (D) staging complete

        const unsigned n  = sh_n;
        const unsigned n1 = n & 0xffffu;
        const unsigned n2 = n >> 16;
        if (t == 0) {
            FENCE_ASYNC();                      // order STS -> async proxy
            if (n1) bulk_store(out4 + off1, sbuf1, n1 * 16u);
            if (n2) bulk_store(out4 + off2, sbuf2, n2 * 16u);
            BULK_COMMIT();
        }
        off1 += n1;
        off2 += n2;
    }

    // ---------- bulk tail zero: this block's slice of [g_total, NROWS) -----
    if (t == 0) BULK_WAIT_READ0();              // buffers free for reuse
    __syncthreads();
    {
        const float4 z = make_float4(0.0f, 0.0f, 0.0f, 0.0f);
        for (int i = t; i < 1024; i += TPB) buf1[i] = z;   // 16 KB of zeros
    }
    __syncthreads();
    if (t == 0) {
        const unsigned total = g_total;
        const unsigned tail  = (unsigned)NROWS - total;
        const unsigned cz    = (tail + NBLK2 - 1) / NBLK2;
        const unsigned s     = total + (unsigned)bk * cz;
        const unsigned e     = min(s + cz, (unsigned)NROWS);
        if (e > s) {
            FENCE_ASYNC();
            unsigned bytes = (e - s) * 16u;
            char* dst = (char*)(out4 + s);
            while (bytes) {
                const unsigned c = bytes < 16384u ? bytes : 16384u;
                bulk_store(dst, sbuf1, c);
                dst += c;
                bytes -= c;
            }
            BULK_COMMIT();
        }
        BULK_WAIT0();                           // all copies fully complete
    }
}

// ---------------------------------------------------------------------------
extern "C" void kernel_launch(void* const* d_in, const int* in_sizes, int n_in,
                              void* d_out, int out_size)
{
    const float* coarse = (const float*)d_in[0];
    float* out = (float*)d_out;

    ms_pass1<<<NBLK1, TPB>>>(coarse, out, out_size);
    ms_pass2<<<NBLK2, TPB>>>((float4*)out);
}

// round 14
// speedup vs baseline: 1.3005x; 1.0037x over previous
#include <cuda_runtime.h>
#include <cuda_bf16.h>
#include <cstdint>

// Problem geometry
#define BATCH   8
#define HIN     1024
#define WIN     1024
#define HC      1025               // code-grid rows
#define WC      1025               // code-grid cols
#define CELLS   (HC * WC)          // 1,050,625 cells per batch
#define WCP     1028               // padded code-row stride (mult of 4)
#define CSTRIDE (HC * WCP)         // per-batch code stride
#define RPB1    8                  // rows per pass1 block
#define NBB1    129                // pass1 chunks per batch: ceil(1025/8)
#define NBLK1   (BATCH * NBB1)     // 1032 pass1 blocks
#define RPB2    2                  // rows per pass2 block (wave balance)
#define NBB2    513                // pass2 chunks per batch: ceil(1025/2)
#define NBLK2   (BATCH * NBB2)     // 4104 pass2 blocks
#define TPB     256
#define NROWS   (2 * BATCH * CELLS)  // 16,810,000 output rows (float4 each)

// -------- scratch (static device globals; no allocation allowed) ----------
__device__ unsigned char g_codes[(size_t)BATCH * CSTRIDE];
__device__ unsigned int  g_cnt1[NBLK2];
__device__ unsigned int  g_cnt2[NBLK2];
__device__ unsigned int  g_off1[NBLK2];
__device__ unsigned int  g_off2[NBLK2];
__device__ unsigned int  g_total;
__device__ unsigned int  g_done;     // zero-init; reset by last block each launch

// Midpoint offsets per code (FIRST table): row = [y+f.x, x+f.y, y+f.z, x+f.w]
__constant__ float4 c_F[16] = {
    { 0.0f,  0.0f,  0.0f,  0.0f},  // 0  (invalid)
    { 0.0f, -0.5f,  0.5f,  0.0f},  // 1
    { 0.5f,  0.0f,  0.0f,  0.5f},  // 2
    { 0.0f, -0.5f,  0.0f,  0.5f},  // 3
    { 0.0f,  0.5f, -0.5f,  0.0f},  // 4
    { 0.0f, -0.5f,  0.5f,  0.0f},  // 5
    { 0.5f,  0.0f, -0.5f,  0.0f},  // 6
    { 0.0f, -0.5f, -0.5f,  0.0f},  // 7
    {-0.5f,  0.0f,  0.0f, -0.5f},  // 8
    {-0.5f,  0.0f,  0.5f,  0.0f},  // 9
    { 0.5f,  0.0f,  0.0f,  0.5f},  // 10
    {-0.5f,  0.0f,  0.0f,  0.5f},  // 11
    { 0.0f,  0.5f,  0.0f, -0.5f},  // 12
    { 0.0f,  0.5f,  0.5f,  0.0f},  // 13
    { 0.5f,  0.0f,  0.0f, -0.5f},  // 14
    { 0.0f,  0.0f,  0.0f,  0.0f},  // 15 (invalid)
};
// SECOND[5] = (0, 0.5, -0.5, 0), SECOND[10] = (-0.5, 0, 0, -0.5) inlined.

// -------- bulk async copy (UBLKCP): shared -> global, zero per-element ops -
__device__ __forceinline__ uint32_t smem_u32(const void* p) {
    uint32_t a;
    asm("{ .reg .u64 t; cvta.to.shared.u64 t, %1; cvt.u32.u64 %0, t; }"
        : "=r"(a) : "l"(p));
    return a;
}
__device__ __forceinline__ void bulk_store(void* gdst, uint32_t ssrc, unsigned bytes) {
    asm volatile("cp.async.bulk.global.shared::cta.bulk_group [%0], [%1], %2;"
        :: "l"(gdst), "r"(ssrc), "r"(bytes) : "memory");
}
#define BULK_COMMIT()     asm volatile("cp.async.bulk.commit_group;" ::: "memory")
#define BULK_WAIT_READ0() asm volatile("cp.async.bulk.wait_group.read 0;" ::: "memory")
#define BULK_WAIT0()      asm volatile("cp.async.bulk.wait_group 0;" ::: "memory")
#define FENCE_ASYNC()     asm volatile("fence.proxy.async.shared::cta;" ::: "memory")

// ------- Pass 1: codes + per-2-row-subchunk counts + inline final scan -----
__global__ __launch_bounds__(TPB, 8)
void ms_pass1(const float* __restrict__ in, float* __restrict__ out, int out_size)
{
    const int bk    = blockIdx.x;
    const int b     = bk / NBB1;
    const int chunk = bk - b * NBB1;
    const int y0    = chunk * RPB1;
    const float* __restrict__ img = in + (size_t)b * HIN * WIN;
    unsigned char* __restrict__ crow0 = g_codes + (size_t)b * CSTRIDE;

    const int t    = threadIdx.x;
    const int col  = 4 * t;
    const int lane = t & 31;
    const int wid  = t >> 5;
    __shared__ unsigned r1[8], r2[8];

    const float* rA = img + (size_t)max(min(y0 - 1, HIN - 1), 0) * WIN;
    float4 vA = *(const float4*)(rA + col);
    float lmA = __shfl_up_sync(0xffffffffu, vA.w, 1);
    if (lane == 0) lmA = (col > 0) ? rA[col - 1] : vA.x;

    #pragma unroll
    for (int sub = 0; sub < 4; sub++) {
        const int ys = y0 + 2 * sub;
        if (ys >= HC) break;
        const int ye = min(ys + 2, HC);
        unsigned c1 = 0, c2 = 0;

        for (int y = ys; y < ye; y++) {
            const float* rB = img + (size_t)min(y, HIN - 1) * WIN;
            float4 vB = *(const float4*)(rB + col);
            float lmB = __shfl_up_sync(0xffffffffu, vB.w, 1);
            if (lane == 0) lmB = (col > 0) ? rB[col - 1] : vB.x;

            const float la[4] = {lmA, vA.x, vA.y, vA.z};
            const float ra[4] = {vA.x, vA.y, vA.z, vA.w};
            const float lb[4] = {lmB, vB.x, vB.y, vB.z};
            const float rb[4] = {vB.x, vB.y, vB.z, vB.w};

            unsigned packed = 0;
            #pragma unroll
            for (int j = 0; j < 4; j++) {
                unsigned code = (lb[j] > 0.0f ? 1u : 0u) | (rb[j] > 0.0f ? 2u : 0u) |
                                (ra[j] > 0.0f ? 4u : 0u) | (la[j] > 0.0f ? 8u : 0u);
                packed |= code << (8 * j);
                c1 += (code - 1u) < 14u;
                c2 += (code == 5u) | (code == 10u);
            }
            unsigned char* crow = crow0 + (size_t)y * WCP;
            *(unsigned int*)(crow + col) = packed;
            if (t == TPB - 1) {
                unsigned code = (vB.w > 0.0f ? 3u : 0u) | (vA.w > 0.0f ? 12u : 0u);
                crow[1024] = (unsigned char)code;
                c1 += (code - 1u) < 14u;
            }
            vA = vB; lmA = lmB;
        }

        unsigned s1 = __reduce_add_sync(0xffffffffu, c1);
        unsigned s2 = __reduce_add_sync(0xffffffffu, c2);
        __syncthreads();
        if (lane == 0) { r1[wid] = s1; r2[wid] = s2; }
        __syncthreads();
        if (t == 0) {
            unsigned t1 = 0, t2 = 0;
            #pragma unroll
            for (int i = 0; i < 8; i++) { t1 += r1[i]; t2 += r2[i]; }
            const int idx = b * NBB2 + chunk * 4 + sub;
            g_cnt1[idx] = t1;
            g_cnt2[idx] = t2;
        }
    }

    // ---- last-block-done: final block performs the global scan inline -----
    __shared__ unsigned slast;
    if (t == 0) {
        __threadfence();
        const bool last = (atomicAdd(&g_done, 1u) == (unsigned)(NBLK1 - 1));
        if (last) g_done = 0;
        slast = last ? 1u : 0u;
    }
    __syncthreads();
    if (!slast) return;
    __threadfence();

    __shared__ unsigned tot[16], gbs[17];
    #pragma unroll
    for (int rep = 0; rep < 2; rep++) {
        const int g = wid * 2 + rep;
        const unsigned* __restrict__ cnt = (g & 1) ? g_cnt2 : g_cnt1;
        const int base = (g >> 1) * NBB2;
        const int i0 = lane * 17;
        unsigned s = 0;
        #pragma unroll
        for (int j = 0; j < 17; j++) {
            const int i = i0 + j;
            if (i < NBB2) s += cnt[base + i];
        }
        s = __reduce_add_sync(0xffffffffu, s);
        if (lane == 0) tot[g] = s;
    }
    __syncthreads();
    if (t == 0) {
        unsigned acc = 0;
        #pragma unroll
        for (int g = 0; g < 16; g++) { gbs[g] = acc; acc += tot[g]; }
        gbs[16] = acc;
        g_total = acc;
    }
    __syncthreads();
    if (t < BATCH && out_size >= NROWS * 4 + BATCH)
        out[(size_t)NROWS * 4 + t] = (float)(tot[2 * t] + tot[2 * t + 1]);

    #pragma unroll
    for (int rep = 0; rep < 2; rep++) {
        const int g = wid * 2 + rep;
        const unsigned* __restrict__ cnt = (g & 1) ? g_cnt2 : g_cnt1;
        unsigned*       __restrict__ off = (g & 1) ? g_off2 : g_off1;
        const int base = (g >> 1) * NBB2;
        const int i0 = lane * 17;
        unsigned v[17];
        unsigned s = 0;
        #pragma unroll
        for (int j = 0; j < 17; j++) {
            const int i = i0 + j;
            v[j] = (i < NBB2) ? cnt[base + i] : 0u;
            s += v[j];
        }
        unsigned incl = s;
        #pragma unroll
        for (int o = 1; o < 32; o <<= 1) {
            const unsigned u = __shfl_up_sync(0xffffffffu, incl, o);
            if (lane >= o) incl += u;
        }
        unsigned run = gbs[g] + incl - s;
        #pragma unroll
        for (int j = 0; j < 17; j++) {
            const int i = i0 + j;
            if (i < NBB2) off[base + i] = run;
            run += v[j];
        }
    }
}

// - Pass 2: buf1-only staging + bulk flush, direct table2, bulk tail zero ---
__global__ __launch_bounds__(TPB, 8)
void ms_pass2(float4* __restrict__ out4)
{
    __shared__ unsigned ws[8];
    __shared__ unsigned sh_n;
    __shared__ float4 buf1[1026];               // 16.4 KB: table-1 staging only

    const int bk   = blockIdx.x;
    const int b    = bk / NBB2;
    const int ci   = bk - b * NBB2;
    const int y0   = ci * RPB2;
    const int nrows = min(y0 + RPB2, HC) - y0;
    const unsigned char* __restrict__ crow0 = g_codes + (size_t)b * CSTRIDE;

    const int t = threadIdx.x;
    const unsigned lane = t & 31u, wid = t >> 5;
    const uint32_t sbuf1 = smem_u32(buf1);

    unsigned off1 = g_off1[bk];
    unsigned off2 = g_off2[bk];

    // prefetch both rows' code words
    unsigned packs[2], cXs[2];
    #pragma unroll
    for (int r = 0; r < 2; r++) {
        if (r < nrows) {
            const unsigned char* crow = crow0 + (size_t)(y0 + r) * WCP;
            packs[r] = *(const unsigned int*)(crow + 4 * t);
            cXs[r]   = (t == TPB - 1) ? (unsigned)crow[1024] : 0u;
        } else { packs[r] = 0u; cXs[r] = 0u; }
    }

    #pragma unroll
    for (int r = 0; r < 2; r++) {
        if (r >= nrows) break;
        const int y = y0 + r;
        const unsigned packed = packs[r];
        unsigned cd[4];
        cd[0] =  packed        & 255u;
        cd[1] = (packed >>  8) & 255u;
        cd[2] = (packed >> 16) & 255u;
        cd[3] =  packed >> 24;
        const unsigned cX = cXs[r];

        unsigned c1 = 0, c2 = 0;
        #pragma unroll
        for (int j = 0; j < 4; j++) {
            c1 += (cd[j] - 1u) < 14u;
            c2 += (cd[j] == 5u) | (cd[j] == 10u);
        }
        c1 += (cX - 1u) < 14u;

        // block exclusive scan (16-bit packed: c1 | c2<<16)
        const unsigned v = c1 | (c2 << 16);
        unsigned inc = v;
        #pragma unroll
        for (int o = 1; o < 32; o <<= 1) {
            const unsigned u = __shfl_up_sync(0xffffffffu, inc, o);
            if (lane >= (unsigned)o) inc += u;
        }
        if (lane == 31) ws[wid] = inc;
        __syncthreads();                        // (A) ws visible
        if (t == 0) {
            unsigned acc = 0;
            #pragma unroll
            for (int i = 0; i < 8; i++) { const unsigned q = ws[i]; ws[i] = acc; acc += q; }
        }
        __syncthreads();                        // (B)
        const unsigned ex = inc - v + ws[wid];
        if (t == TPB - 1) sh_n = ex + v;
        unsigned p1 = ex & 0xffffu;
        unsigned q2 = off2 + (ex >> 16);        // direct gmem position (table 2)

        // wait until prior row's bulk copy has READ buf1
        if (t == 0) BULK_WAIT_READ0();
        __syncthreads();                        // (C) safe to overwrite buf; sh_n visible

        const float fy = (float)y;
        const float fx = (float)(4 * t);
        #pragma unroll
        for (int j = 0; j < 4; j++) {
            const unsigned code = cd[j];
            const float cx = fx + (float)j;
            if ((code - 1u) < 14u) {
                const float4 f = c_F[code];
                buf1[p1++] = make_float4(fy + f.x, cx + f.y, fy + f.z, cx + f.w);
            }
            if (code == 5u)
                __stwt(&out4[q2++], make_float4(fy, cx + 0.5f, fy - 0.5f, cx));
            else if (code == 10u)
                __stwt(&out4[q2++], make_float4(fy - 0.5f, cx, fy, cx - 0.5f));
        }
        if (t == TPB - 1 && (cX - 1u) < 14u) {
            const float4 f = c_F[cX];
            buf1[p1++] = make_float4(fy + f.x, 1024.0f + f.y, fy + f.z, 1024.0f + f.w);
        }
        __syncthreads();                        // (D) staging complete

        const unsigned n  = sh_n;
        const unsigned n1 = n & 0xffffu;
        if (t == 0) {
            FENCE_ASYNC();                      // order STS -> async proxy
            if (n1) bulk_store(out4 + off1, sbuf1, n1 * 16u);
            BULK_COMMIT();
        }
        off1 += n1;
        off2 += (n >> 16);
    }

    // ---------- bulk tail zero: this block's slice of [g_total, NROWS) -----
    if (t == 0) BULK_WAIT_READ0();              // buf1 free for reuse
    __syncthreads();
    {
        const float4 z = make_float4(0.0f, 0.0f, 0.0f, 0.0f);
        for (int i = t; i < 1024; i += TPB) buf1[i] = z;   // 16 KB of zeros
    }
    __syncthreads();
    if (t == 0) {
        const unsigned total = g_total;
        const unsigned tail  = (unsigned)NROWS - total;
        const unsigned cz    = (tail + NBLK2 - 1) / NBLK2;
        const unsigned s     = total + (unsigned)bk * cz;
        const unsigned e     = min(s + cz, (unsigned)NROWS);
        if (e > s) {
            FENCE_ASYNC();
            unsigned bytes = (e - s) * 16u;
            char* dst = (char*)(out4 + s);
            while (bytes) {
                const unsigned c = bytes < 16384u ? bytes : 16384u;
                bulk_store(dst, sbuf1, c);
                dst += c;
                bytes -= c;
            }
            BULK_COMMIT();
        }
        BULK_WAIT0();                           // all copies fully complete
    }
}

// ---------------------------------------------------------------------------
extern "C" void kernel_launch(void* const* d_in, const int* in_sizes, int n_in,
                              void* d_out, int out_size)
{
    const float* coarse = (const float*)d_in[0];
    float* out = (float*)d_out;

    ms_pass1<<<NBLK1, TPB>>>(coarse, out, out_size);
    ms_pass2<<<NBLK2, TPB>>>((float4*)out);
}

// round 15
// speedup vs baseline: 1.3436x; 1.0331x over previous
#include <cuda_runtime.h>
#include <cuda_bf16.h>
#include <cstdint>

// Problem geometry
#define BATCH   8
#define HIN     1024
#define WIN     1024
#define HC      1025               // code-grid rows
#define WC      1025               // code-grid cols
#define CELLS   (HC * WC)          // 1,050,625 cells per batch
#define WCP     1028               // padded code-row stride (mult of 4)
#define CSTRIDE (HC * WCP)         // per-batch code stride
#define RPB1    8                  // rows per pass1 block
#define NBB1    129                // pass1 chunks per batch: ceil(1025/8)
#define NBLK1   (BATCH * NBB1)     // 1032 pass1 blocks
#define RPB2    4                  // rows per pass2 block
#define NBB2    257                // pass2 chunks per batch: ceil(1025/4)
#define NBLK2   (BATCH * NBB2)     // 2056 pass2 blocks
#define TPB     256
#define NROWS   (2 * BATCH * CELLS)  // 16,810,000 output rows (float4 each)

// -------- scratch (static device globals; no allocation allowed) ----------
__device__ unsigned char g_codes[(size_t)BATCH * CSTRIDE];
__device__ unsigned int  g_cnt1[NBLK2];
__device__ unsigned int  g_cnt2[NBLK2];
__device__ unsigned int  g_off1[NBLK2];
__device__ unsigned int  g_off2[NBLK2];
__device__ unsigned int  g_total;
__device__ unsigned int  g_done;     // zero-init; reset by last block each launch

// Midpoint offsets per code (FIRST table): row = [y+f.x, x+f.y, y+f.z, x+f.w]
__constant__ float4 c_F[16] = {
    { 0.0f,  0.0f,  0.0f,  0.0f},  // 0  (invalid)
    { 0.0f, -0.5f,  0.5f,  0.0f},  // 1
    { 0.5f,  0.0f,  0.0f,  0.5f},  // 2
    { 0.0f, -0.5f,  0.0f,  0.5f},  // 3
    { 0.0f,  0.5f, -0.5f,  0.0f},  // 4
    { 0.0f, -0.5f,  0.5f,  0.0f},  // 5
    { 0.5f,  0.0f, -0.5f,  0.0f},  // 6
    { 0.0f, -0.5f, -0.5f,  0.0f},  // 7
    {-0.5f,  0.0f,  0.0f, -0.5f},  // 8
    {-0.5f,  0.0f,  0.5f,  0.0f},  // 9
    { 0.5f,  0.0f,  0.0f,  0.5f},  // 10
    {-0.5f,  0.0f,  0.0f,  0.5f},  // 11
    { 0.0f,  0.5f,  0.0f, -0.5f},  // 12
    { 0.0f,  0.5f,  0.5f,  0.0f},  // 13
    { 0.5f,  0.0f,  0.0f, -0.5f},  // 14
    { 0.0f,  0.0f,  0.0f,  0.0f},  // 15 (invalid)
};
// SECOND[5] = (0, 0.5, -0.5, 0), SECOND[10] = (-0.5, 0, 0, -0.5) inlined.

// -------- bulk async copy (UBLKCP): shared -> global, zero per-element ops -
__device__ __forceinline__ uint32_t smem_u32(const void* p) {
    uint32_t a;
    asm("{ .reg .u64 t; cvta.to.shared.u64 t, %1; cvt.u32.u64 %0, t; }"
        : "=r"(a) : "l"(p));
    return a;
}
__device__ __forceinline__ void bulk_store(void* gdst, uint32_t ssrc, unsigned bytes) {
    asm volatile("cp.async.bulk.global.shared::cta.bulk_group [%0], [%1], %2;"
        :: "l"(gdst), "r"(ssrc), "r"(bytes) : "memory");
}
#define BULK_COMMIT()     asm volatile("cp.async.bulk.commit_group;" ::: "memory")
#define BULK_WAIT_READ1() asm volatile("cp.async.bulk.wait_group.read 1;" ::: "memory")
#define BULK_WAIT_READ0() asm volatile("cp.async.bulk.wait_group.read 0;" ::: "memory")
#define BULK_WAIT0()      asm volatile("cp.async.bulk.wait_group 0;" ::: "memory")
#define FENCE_ASYNC()     asm volatile("fence.proxy.async.shared::cta;" ::: "memory")

// ------- Pass 1: codes + per-4-row-subchunk counts + inline final scan -----
__global__ __launch_bounds__(TPB, 8)
void ms_pass1(const float* __restrict__ in, float* __restrict__ out, int out_size)
{
    const int bk    = blockIdx.x;
    const int b     = bk / NBB1;
    const int chunk = bk - b * NBB1;
    const int y0    = chunk * RPB1;
    const float* __restrict__ img = in + (size_t)b * HIN * WIN;
    unsigned char* __restrict__ crow0 = g_codes + (size_t)b * CSTRIDE;

    const int t    = threadIdx.x;
    const int col  = 4 * t;
    const int lane = t & 31;
    const int wid  = t >> 5;
    __shared__ unsigned r1[8], r2[8];

    const float* rA = img + (size_t)max(min(y0 - 1, HIN - 1), 0) * WIN;
    float4 vA = *(const float4*)(rA + col);
    float lmA = __shfl_up_sync(0xffffffffu, vA.w, 1);
    if (lane == 0) lmA = (col > 0) ? rA[col - 1] : vA.x;

    #pragma unroll
    for (int sub = 0; sub < 2; sub++) {          // 2 subchunks of 4 rows
        const int ys = y0 + 4 * sub;
        if (ys >= HC) break;
        const int ye = min(ys + 4, HC);
        unsigned c1 = 0, c2 = 0;

        for (int y = ys; y < ye; y++) {
            const float* rB = img + (size_t)min(y, HIN - 1) * WIN;
            float4 vB = *(const float4*)(rB + col);
            float lmB = __shfl_up_sync(0xffffffffu, vB.w, 1);
            if (lane == 0) lmB = (col > 0) ? rB[col - 1] : vB.x;

            const float la[4] = {lmA, vA.x, vA.y, vA.z};
            const float ra[4] = {vA.x, vA.y, vA.z, vA.w};
            const float lb[4] = {lmB, vB.x, vB.y, vB.z};
            const float rb[4] = {vB.x, vB.y, vB.z, vB.w};

            unsigned packed = 0;
            #pragma unroll
            for (int j = 0; j < 4; j++) {
                unsigned code = (lb[j] > 0.0f ? 1u : 0u) | (rb[j] > 0.0f ? 2u : 0u) |
                                (ra[j] > 0.0f ? 4u : 0u) | (la[j] > 0.0f ? 8u : 0u);
                packed |= code << (8 * j);
                c1 += (code - 1u) < 14u;
                c2 += (code == 5u) | (code == 10u);
            }
            unsigned char* crow = crow0 + (size_t)y * WCP;
            *(unsigned int*)(crow + col) = packed;
            if (t == TPB - 1) {
                unsigned code = (vB.w > 0.0f ? 3u : 0u) | (vA.w > 0.0f ? 12u : 0u);
                crow[1024] = (unsigned char)code;
                c1 += (code - 1u) < 14u;
            }
            vA = vB; lmA = lmB;
        }

        unsigned s1 = __reduce_add_sync(0xffffffffu, c1);
        unsigned s2 = __reduce_add_sync(0xffffffffu, c2);
        __syncthreads();
        if (lane == 0) { r1[wid] = s1; r2[wid] = s2; }
        __syncthreads();
        if (t == 0) {
            unsigned t1 = 0, t2 = 0;
            #pragma unroll
            for (int i = 0; i < 8; i++) { t1 += r1[i]; t2 += r2[i]; }
            const int idx = b * NBB2 + chunk * 2 + sub;
            g_cnt1[idx] = t1;
            g_cnt2[idx] = t2;
        }
    }

    // ---- last-block-done: final block performs the global scan inline -----
    __shared__ unsigned slast;
    if (t == 0) {
        __threadfence();
        const bool last = (atomicAdd(&g_done, 1u) == (unsigned)(NBLK1 - 1));
        if (last) g_done = 0;
        slast = last ? 1u : 0u;
    }
    __syncthreads();
    if (!slast) {
        cudaTriggerProgrammaticLaunchCompletion();   // codes+counts published
        return;
    }
    __threadfence();

    __shared__ unsigned tot[16], gbs[17];
    #pragma unroll
    for (int rep = 0; rep < 2; rep++) {
        const int g = wid * 2 + rep;
        const unsigned* __restrict__ cnt = (g & 1) ? g_cnt2 : g_cnt1;
        const int base = (g >> 1) * NBB2;
        const int i0 = lane * 9;                    // 32*9 = 288 >= 257
        unsigned s = 0;
        #pragma unroll
        for (int j = 0; j < 9; j++) {
            const int i = i0 + j;
            if (i < NBB2) s += cnt[base + i];
        }
        s = __reduce_add_sync(0xffffffffu, s);
        if (lane == 0) tot[g] = s;
    }
    __syncthreads();
    if (t == 0) {
        unsigned acc = 0;
        #pragma unroll
        for (int g = 0; g < 16; g++) { gbs[g] = acc; acc += tot[g]; }
        gbs[16] = acc;
        g_total = acc;
    }
    __syncthreads();
    if (t < BATCH && out_size >= NROWS * 4 + BATCH)
        out[(size_t)NROWS * 4 + t] = (float)(tot[2 * t] + tot[2 * t + 1]);

    #pragma unroll
    for (int rep = 0; rep < 2; rep++) {
        const int g = wid * 2 + rep;
        const unsigned* __restrict__ cnt = (g & 1) ? g_cnt2 : g_cnt1;
        unsigned*       __restrict__ off = (g & 1) ? g_off2 : g_off1;
        const int base = (g >> 1) * NBB2;
        const int i0 = lane * 9;
        unsigned v[9];
        unsigned s = 0;
        #pragma unroll
        for (int j = 0; j < 9; j++) {
            const int i = i0 + j;
            v[j] = (i < NBB2) ? cnt[base + i] : 0u;
            s += v[j];
        }
        unsigned incl = s;
        #pragma unroll
        for (int o = 1; o < 32; o <<= 1) {
            const unsigned u = __shfl_up_sync(0xffffffffu, incl, o);
            if (lane >= o) incl += u;
        }
        unsigned run = gbs[g] + incl - s;
        #pragma unroll
        for (int j = 0; j < 9; j++) {
            const int i = i0 + j;
            if (i < NBB2) off[base + i] = run;
            run += v[j];
        }
    }
    __syncthreads();
    cudaTriggerProgrammaticLaunchCompletion();       // offsets published
}

// - Pass 2: double-buffered bulk staging, direct table2, bulk tail zero -----
__global__ __launch_bounds__(TPB)
void ms_pass2(float4* __restrict__ out4)
{
    cudaGridDependencySynchronize();                 // PDL: wait for pass1 data

    __shared__ unsigned ws[8];
    __shared__ unsigned sh_n;
    __shared__ float4 buf[2][1026];                  // double buffer: 32.8 KB

    const int bk   = blockIdx.x;
    const int b    = bk / NBB2;
    const int ci   = bk - b * NBB2;
    const int y0   = ci * RPB2;
    const int nrows = min(y0 + RPB2, HC) - y0;
    const unsigned char* __restrict__ crow0 = g_codes + (size_t)b * CSTRIDE;

    const int t = threadIdx.x;
    const unsigned lane = t & 31u, wid = t >> 5;
    const uint32_t sbuf[2] = { smem_u32(buf[0]), smem_u32(buf[1]) };

    unsigned off1 = g_off1[bk];
    unsigned off2 = g_off2[bk];

    // prefetch all rows' code words (MLP)
    unsigned packs[RPB2], cXs[RPB2];
    #pragma unroll
    for (int r = 0; r < RPB2; r++) {
        if (r < nrows) {
            const unsigned char* crow = crow0 + (size_t)(y0 + r) * WCP;
            packs[r] = *(const unsigned int*)(crow + 4 * t);
            cXs[r]   = (t == TPB - 1) ? (unsigned)crow[1024] : 0u;
        } else { packs[r] = 0u; cXs[r] = 0u; }
    }

    #pragma unroll
    for (int r = 0; r < RPB2; r++) {
        if (r >= nrows) break;
        const int y = y0 + r;
        const unsigned packed = packs[r];
        unsigned cd[4];
        cd[0] =  packed        & 255u;
        cd[1] = (packed >>  8) & 255u;
        cd[2] = (packed >> 16) & 255u;
        cd[3] =  packed >> 24;
        const unsigned cX = cXs[r];

        unsigned c1 = 0, c2 = 0;
        #pragma unroll
        for (int j = 0; j < 4; j++) {
            c1 += (cd[j] - 1u) < 14u;
            c2 += (cd[j] == 5u) | (cd[j] == 10u);
        }
        c1 += (cX - 1u) < 14u;

        // block exclusive scan (16-bit packed: c1 | c2<<16)
        const unsigned v = c1 | (c2 << 16);
        unsigned inc = v;
        #pragma unroll
        for (int o = 1; o < 32; o <<= 1) {
            const unsigned u = __shfl_up_sync(0xffffffffu, inc, o);
            if (lane >= (unsigned)o) inc += u;
        }
        if (lane == 31) ws[wid] = inc;
        __syncthreads();                        // (A) ws visible
        if (t == 0) {
            unsigned acc = 0;
            #pragma unroll
            for (int i = 0; i < 8; i++) { const unsigned q = ws[i]; ws[i] = acc; acc += q; }
            sh_n = acc;                          // block totals (both fields)
            BULK_WAIT_READ1();                   // buf[r&1] (from row r-2) free
        }
        __syncthreads();                        // (B) ws+sh_n valid, buffer free
        const unsigned ex = inc - v + ws[wid];
        unsigned p1 = ex & 0xffffu;
        unsigned q2 = off2 + (ex >> 16);         // direct gmem position (table 2)

        float4* bptr = buf[r & 1];
        const float fy = (float)y;
        const float fx = (float)(4 * t);
        #pragma unroll
        for (int j = 0; j < 4; j++) {
            const unsigned code = cd[j];
            const float cx = fx + (float)j;
            if ((code - 1u) < 14u) {
                const float4 f = c_F[code];
                bptr[p1++] = make_float4(fy + f.x, cx + f.y, fy + f.z, cx + f.w);
            }
            if (code == 5u)
                __stwt(&out4[q2++], make_float4(fy, cx + 0.5f, fy - 0.5f, cx));
            else if (code == 10u)
                __stwt(&out4[q2++], make_float4(fy - 0.5f, cx, fy, cx - 0.5f));
        }
        if (t == TPB - 1 && (cX - 1u) < 14u) {
            const float4 f = c_F[cX];
            bptr[p1++] = make_float4(fy + f.x, 1024.0f + f.y, fy + f.z, 1024.0f + f.w);
        }
        __syncthreads();                        // (D) staging complete

        const unsigned n  = sh_n;
        const unsigned n1 = n & 0xffffu;
        if (t == 0) {
            FENCE_ASYNC();                      // order STS -> async proxy
            if (n1) bulk_store(out4 + off1, sbuf[r & 1], n1 * 16u);
            BULK_COMMIT();
        }
        off1 += n1;
        off2 += (n >> 16);
    }

    // ---------- bulk tail zero: this block's slice of [g_total, NROWS) -----
    if (t == 0) BULK_WAIT_READ0();              // both buffers free
    __syncthreads();
    {
        const float4 z = make_float4(0.0f, 0.0f, 0.0f, 0.0f);
        for (int i = t; i < 1024; i += TPB) buf[0][i] = z;   // 16 KB of zeros
    }
    __syncthreads();
    if (t == 0) {
        const unsigned total = g_total;
        const unsigned tail  = (unsigned)NROWS - total;
        const unsigned cz    = (tail + NBLK2 - 1) / NBLK2;
        const unsigned s     = total + (unsigned)bk * cz;
        const unsigned e     = min(s + cz, (unsigned)NROWS);
        if (e > s) {
            FENCE_ASYNC();
            unsigned bytes = (e - s) * 16u;
            char* dst = (char*)(out4 + s);
            while (bytes) {
                const unsigned c = bytes < 16384u ? bytes : 16384u;
                bulk_store(dst, sbuf[0], c);
                dst += c;
                bytes -= c;
            }
            BULK_COMMIT();
        }
        BULK_WAIT0();                           // all copies fully complete
    }
}

// ---------------------------------------------------------------------------
extern "C" void kernel_launch(void* const* d_in, const int* in_sizes, int n_in,
                              void* d_out, int out_size)
{
    const float* coarse = (const float*)d_in[0];
    float* out = (float*)d_out;

    ms_pass1<<<NBLK1, TPB>>>(coarse, out, out_size);

    // PDL: pass2 launches while pass1 drains; data ordered by
    // cudaGridDependencySynchronize() in pass2.
    cudaLaunchConfig_t cfg = {};
    cfg.gridDim  = dim3(NBLK2);
    cfg.blockDim = dim3(TPB);
    cfg.dynamicSmemBytes = 0;
    cfg.stream = 0;
    cudaLaunchAttribute attrs[1];
    attrs[0].id = cudaLaunchAttributeProgrammaticStreamSerialization;
    attrs[0].val.programmaticStreamSerializationAllowed = 1;
    cfg.attrs = attrs;
    cfg.numAttrs = 1;
    cudaLaunchKernelEx(&cfg, ms_pass2, (float4*)out);
}